// round 4
// baseline (speedup 1.0000x reference)
#include <cuda_runtime.h>
#include <cuda_bf16.h>

// Scales: S={56,28,14,7}, C={64,128,256,512}, HW={3136,784,196,49}
// HWC scratch offsets (floats): 0, 200704, 301056, 351232; total 376320 floats.
#define HWC_TOTAL 376320
#define NPTS_MAX  131072

__device__ float g_hwc[HWC_TOTAL];
__device__ int4  g_off[NPTS_MAX];   // per-point, per-scale float-offset of pixel base, -1 if zero row

// Pre-pass: (a) transpose batch-b CHW slices -> HWC scratch,
//           (b) per-point projected coords -> per-scale gather offsets (or -1).
__global__ void prep_kernel(const float* __restrict__ f0, const float* __restrict__ f1,
                            const float* __restrict__ f2, const float* __restrict__ f3,
                            const float* __restrict__ pts, const int* __restrict__ bptr,
                            int N)
{
    int tid = blockIdx.x * blockDim.x + threadIdx.x;
    if (tid < HWC_TOTAL) {
        int b = bptr ? *bptr : 3;
        const float* src; int e, clog2, HW;
        if (tid < 200704)      { src = f0; e = tid;          clog2 = 6; HW = 3136; }
        else if (tid < 301056) { src = f1; e = tid - 200704; clog2 = 7; HW = 784;  }
        else if (tid < 351232) { src = f2; e = tid - 301056; clog2 = 8; HW = 196;  }
        else                   { src = f3; e = tid - 351232; clog2 = 9; HW = 49;   }
        int C = 1 << clog2;
        int c = e & (C - 1);       // channel (fastest in dst)
        int p = e >> clog2;        // pixel index
        g_hwc[tid] = src[(size_t)b * C * HW + (size_t)c * HW + p];
    } else {
        int n = tid - HWC_TOTAL;
        if (n < N) {
            float p0 = pts[3 * n + 0];
            float p1 = pts[3 * n + 1];
            float p2 = pts[3 * n + 2];
            float h = 248.0f * (p1 / p2) + 111.5f;
            float w = 248.0f * (p0 / (-p2)) + 111.5f;
            h = fminf(fmaxf(h, 0.0f), 223.0f);
            w = fminf(fmaxf(w, 0.0f), 223.0f);

            const int   S[4]    = {56, 28, 14, 7};
            const int   C[4]    = {64, 128, 256, 512};
            const int   base[4] = {0, 200704, 301056, 351232};
            const float inv[4]  = {0.25f, 0.125f, 0.0625f, 0.03125f};

            int4 r;
            int* rp = (int*)&r;
            #pragma unroll
            for (int s = 0; s < 4; s++) {
                float x = h * inv[s];   // == h / (224/S): divisor is an exact power of two
                float y = w * inv[s];
                int x1 = (int)floorf(x);
                int y1 = (int)floorf(y);
                int x2 = min((int)ceilf(x), S[s] - 1);
                int y2 = min((int)ceilf(y), S[s] - 1);
                // reference truncates before weighting, so only w11=(x2-x1)*(y2-y1) in {0,1} survives
                int wgt = (x2 - x1) * (y2 - y1);
                rp[s] = wgt ? (base[s] + (x1 * S[s] + y1) * C[s]) : -1;
            }
            g_off[n] = r;
        }
    }
}

// Main kernel: one thread per (point, 4-float4 group). 960 floats/point = 240 float4 = 60 groups.
// sub [0,4): scale0; [4,12): scale1; [12,28): scale2; [28,60): scale3.
// Region boundaries are multiples of 4 groups, so a group never straddles scales.
__global__ void gather_kernel(float4* __restrict__ out, int N)
{
    int gid = blockIdx.x * blockDim.x + threadIdx.x;
    unsigned n = (unsigned)gid / 60u;
    if (n >= (unsigned)N) return;
    int sub = gid - (int)n * 60;

    int4 off4 = g_off[n];
    int off, c4;
    if (sub < 4)       { off = off4.x; c4 = sub * 4;        }
    else if (sub < 12) { off = off4.y; c4 = (sub - 4) * 4;  }
    else if (sub < 28) { off = off4.z; c4 = (sub - 12) * 4; }
    else               { off = off4.w; c4 = (sub - 28) * 4; }

    float4 v0 = make_float4(0.f, 0.f, 0.f, 0.f);
    float4 v1 = v0, v2 = v0, v3 = v0;
    if (off >= 0) {
        const float4* src = (const float4*)&g_hwc[off];
        v0 = src[c4 + 0];
        v1 = src[c4 + 1];
        v2 = src[c4 + 2];
        v3 = src[c4 + 3];
    }
    float4* dst = out + (size_t)n * 240 + sub * 4;
    dst[0] = v0;
    dst[1] = v1;
    dst[2] = v2;
    dst[3] = v3;
}

extern "C" void kernel_launch(void* const* d_in, const int* in_sizes, int n_in,
                              void* d_out, int out_size)
{
    const float* f0  = (const float*)d_in[0];
    const float* f1  = (const float*)d_in[1];
    const float* f2  = (const float*)d_in[2];
    const float* f3  = (const float*)d_in[3];
    const float* pts = (const float*)d_in[4];
    const int*   bp  = (n_in >= 6) ? (const int*)d_in[5] : nullptr;

    int N = in_sizes[4] / 3;
    if (N > NPTS_MAX) N = NPTS_MAX;

    {
        int total = HWC_TOTAL + N;
        int threads = 256;
        int blocks = (total + threads - 1) / threads;
        prep_kernel<<<blocks, threads>>>(f0, f1, f2, f3, pts, bp, N);
    }
    {
        long long total = (long long)N * 60;
        int threads = 256;
        int blocks = (int)((total + threads - 1) / threads);
        gather_kernel<<<blocks, threads>>>((float4*)d_out, N);
    }
}

// round 5
// speedup vs baseline: 1.1567x; 1.1567x over previous
#include <cuda_runtime.h>
#include <cuda_bf16.h>

// Scales: S={56,28,14,7}, C={64,128,256,512}, HW={3136,784,196,49}
// HWC scratch offsets (floats): 0, 200704, 301056, 351232; total 376320 floats.
#define HWC_TOTAL 376320
#define NPTS_MAX  131072

__device__ float g_hwc[HWC_TOTAL];
__device__ int4  g_off[NPTS_MAX];   // per-point, per-scale float-offset of pixel base, -1 if zero row

// Pre-pass: (a) transpose batch-b CHW slices -> HWC scratch,
//           (b) per-point projected coords -> per-scale gather offsets (or -1).
__global__ void prep_kernel(const float* __restrict__ f0, const float* __restrict__ f1,
                            const float* __restrict__ f2, const float* __restrict__ f3,
                            const float* __restrict__ pts, const int* __restrict__ bptr,
                            int N)
{
    int tid = blockIdx.x * blockDim.x + threadIdx.x;
    if (tid < HWC_TOTAL) {
        int b = bptr ? *bptr : 3;
        const float* src; int e, clog2, HW;
        if (tid < 200704)      { src = f0; e = tid;          clog2 = 6; HW = 3136; }
        else if (tid < 301056) { src = f1; e = tid - 200704; clog2 = 7; HW = 784;  }
        else if (tid < 351232) { src = f2; e = tid - 301056; clog2 = 8; HW = 196;  }
        else                   { src = f3; e = tid - 351232; clog2 = 9; HW = 49;   }
        int C = 1 << clog2;
        int c = e & (C - 1);       // channel (fastest in dst)
        int p = e >> clog2;        // pixel index
        g_hwc[tid] = src[(size_t)b * C * HW + (size_t)c * HW + p];
    } else {
        int n = tid - HWC_TOTAL;
        if (n < N) {
            float p0 = pts[3 * n + 0];
            float p1 = pts[3 * n + 1];
            float p2 = pts[3 * n + 2];
            float h = 248.0f * (p1 / p2) + 111.5f;
            float w = 248.0f * (p0 / (-p2)) + 111.5f;
            h = fminf(fmaxf(h, 0.0f), 223.0f);
            w = fminf(fmaxf(w, 0.0f), 223.0f);

            const int   S[4]    = {56, 28, 14, 7};
            const int   C[4]    = {64, 128, 256, 512};
            const int   base[4] = {0, 200704, 301056, 351232};
            const float inv[4]  = {0.25f, 0.125f, 0.0625f, 0.03125f};

            int4 r;
            int* rp = (int*)&r;
            #pragma unroll
            for (int s = 0; s < 4; s++) {
                float x = h * inv[s];   // == h / (224/S): divisor is an exact power of two
                float y = w * inv[s];
                int x1 = (int)floorf(x);
                int y1 = (int)floorf(y);
                int x2 = min((int)ceilf(x), S[s] - 1);
                int y2 = min((int)ceilf(y), S[s] - 1);
                // reference truncates before weighting, so only w11=(x2-x1)*(y2-y1) in {0,1} survives
                int wgt = (x2 - x1) * (y2 - y1);
                rp[s] = wgt ? (base[s] + (x1 * S[s] + y1) * C[s]) : -1;
            }
            g_off[n] = r;
        }
    }
}

// Main kernel: one thread per float4, fully coalesced (consecutive lanes ->
// consecutive 16B => every warp store instruction covers 512B contiguous,
// all sectors full). All projection math is precomputed in g_off.
// chunk [0,16): scale0; [16,48): scale1; [48,112): scale2; [112,240): scale3.
__global__ void gather_kernel(float4* __restrict__ out, int N)
{
    int gid = blockIdx.x * blockDim.x + threadIdx.x;
    unsigned n = (unsigned)gid / 240u;   // umulhi const-division
    if (n >= (unsigned)N) return;
    int chunk = gid - (int)n * 240;

    int4 off4 = __ldg(&g_off[n]);        // broadcast across 240 consecutive threads

    int off, c4;
    if (chunk < 16)       { off = off4.x; c4 = chunk;       }
    else if (chunk < 48)  { off = off4.y; c4 = chunk - 16;  }
    else if (chunk < 112) { off = off4.z; c4 = chunk - 48;  }
    else                  { off = off4.w; c4 = chunk - 112; }

    float4 v = make_float4(0.f, 0.f, 0.f, 0.f);
    if (off >= 0) {
        v = *(const float4*)&g_hwc[off + c4 * 4];   // L2-resident gather
    }
    out[gid] = v;
}

extern "C" void kernel_launch(void* const* d_in, const int* in_sizes, int n_in,
                              void* d_out, int out_size)
{
    const float* f0  = (const float*)d_in[0];
    const float* f1  = (const float*)d_in[1];
    const float* f2  = (const float*)d_in[2];
    const float* f3  = (const float*)d_in[3];
    const float* pts = (const float*)d_in[4];
    const int*   bp  = (n_in >= 6) ? (const int*)d_in[5] : nullptr;

    int N = in_sizes[4] / 3;
    if (N > NPTS_MAX) N = NPTS_MAX;

    {
        int total = HWC_TOTAL + N;
        int threads = 256;
        int blocks = (total + threads - 1) / threads;
        prep_kernel<<<blocks, threads>>>(f0, f1, f2, f3, pts, bp, N);
    }
    {
        long long total = (long long)N * 240;
        int threads = 256;
        int blocks = (int)((total + threads - 1) / threads);
        gather_kernel<<<blocks, threads>>>((float4*)d_out, N);
    }
}

// round 8
// speedup vs baseline: 1.6796x; 1.4521x over previous
#include <cuda_runtime.h>
#include <cuda_bf16.h>

// Scales: S={56,28,14,7}, C={64,128,256,512}, HW={3136,784,196,49}
// HWC scratch offsets (floats): 0, 200704, 301056, 351232; total 376320 floats.
#define HWC_TOTAL 376320
#define NPTS_MAX  131072
#define PTS_PER_BLK 16

__device__ float g_hwc[HWC_TOTAL];
__device__ int4  g_off[NPTS_MAX];   // per-point, per-scale float-offset of pixel base, -1 if zero row

// Pre-pass: (a) transpose batch-b CHW slices -> HWC scratch,
//           (b) per-point projected coords -> per-scale gather offsets (or -1).
__global__ void prep_kernel(const float* __restrict__ f0, const float* __restrict__ f1,
                            const float* __restrict__ f2, const float* __restrict__ f3,
                            const float* __restrict__ pts, const int* __restrict__ bptr,
                            int N)
{
    int tid = blockIdx.x * blockDim.x + threadIdx.x;
    if (tid < HWC_TOTAL) {
        int b = bptr ? *bptr : 3;
        const float* src; int e, clog2, HW;
        if (tid < 200704)      { src = f0; e = tid;          clog2 = 6; HW = 3136; }
        else if (tid < 301056) { src = f1; e = tid - 200704; clog2 = 7; HW = 784;  }
        else if (tid < 351232) { src = f2; e = tid - 301056; clog2 = 8; HW = 196;  }
        else                   { src = f3; e = tid - 351232; clog2 = 9; HW = 49;   }
        int C = 1 << clog2;
        int c = e & (C - 1);       // channel (fastest in dst)
        int p = e >> clog2;        // pixel index
        g_hwc[tid] = src[(size_t)b * C * HW + (size_t)c * HW + p];
    } else {
        int n = tid - HWC_TOTAL;
        if (n < N) {
            float p0 = pts[3 * n + 0];
            float p1 = pts[3 * n + 1];
            float p2 = pts[3 * n + 2];
            float h = 248.0f * (p1 / p2) + 111.5f;
            float w = 248.0f * (p0 / (-p2)) + 111.5f;
            h = fminf(fmaxf(h, 0.0f), 223.0f);
            w = fminf(fmaxf(w, 0.0f), 223.0f);

            const int   S[4]    = {56, 28, 14, 7};
            const int   C[4]    = {64, 128, 256, 512};
            const int   base[4] = {0, 200704, 301056, 351232};
            const float inv[4]  = {0.25f, 0.125f, 0.0625f, 0.03125f};

            int4 r;
            int* rp = (int*)&r;
            #pragma unroll
            for (int s = 0; s < 4; s++) {
                float x = h * inv[s];   // == h / (224/S): divisor is an exact power of two
                float y = w * inv[s];
                int x1 = (int)floorf(x);
                int y1 = (int)floorf(y);
                int x2 = min((int)ceilf(x), S[s] - 1);
                int y2 = min((int)ceilf(y), S[s] - 1);
                // reference truncates before weighting, so only w11=(x2-x1)*(y2-y1) in {0,1} survives
                int wgt = (x2 - x1) * (y2 - y1);
                rp[s] = wgt ? (base[s] + (x1 * S[s] + y1) * C[s]) : -1;
            }
            g_off[n] = r;
        }
    }
}

// Main kernel: each 256-thread block owns PTS_PER_BLK consecutive points.
// Threads 0..239 each own a fixed float4 chunk of the 960-float row, so the
// scale-region selection is loop-invariant; the k-loop over points is unrolled
// x4 so each thread keeps 4 independent L2-hit gathers in flight (MLP=4)
// before the 4 coalesced streaming stores.
// chunk [0,16): scale0; [16,48): scale1; [48,112): scale2; [112,240): scale3.
__global__ void __launch_bounds__(256) gather_kernel(float4* __restrict__ out, int N)
{
    int tid = threadIdx.x;
    if (tid >= 240) return;
    int p0 = blockIdx.x * PTS_PER_BLK;

    // Loop-invariant: which component of off4 this thread uses, and its c4.
    int comp, c4;
    if (tid < 16)       { comp = 0; c4 = tid;       }
    else if (tid < 48)  { comp = 1; c4 = tid - 16;  }
    else if (tid < 112) { comp = 2; c4 = tid - 48;  }
    else                { comp = 3; c4 = tid - 112; }
    int c16 = c4 * 4;

    #pragma unroll 1
    for (int kb = 0; kb < PTS_PER_BLK; kb += 4) {
        float4 v[4];
        #pragma unroll
        for (int j = 0; j < 4; j++) {
            int p = p0 + kb + j;
            v[j] = make_float4(0.f, 0.f, 0.f, 0.f);
            if (p < N) {
                int4 o4 = __ldg(&g_off[p]);     // broadcast within warp
                int off = (comp == 0) ? o4.x : (comp == 1) ? o4.y
                        : (comp == 2) ? o4.z : o4.w;
                if (off >= 0)
                    v[j] = __ldg((const float4*)&g_hwc[off + c16]);
            }
        }
        #pragma unroll
        for (int j = 0; j < 4; j++) {
            int p = p0 + kb + j;
            if (p < N)
                __stcs(&out[(size_t)p * 240 + tid], v[j]);
        }
    }
}

extern "C" void kernel_launch(void* const* d_in, const int* in_sizes, int n_in,
                              void* d_out, int out_size)
{
    const float* f0  = (const float*)d_in[0];
    const float* f1  = (const float*)d_in[1];
    const float* f2  = (const float*)d_in[2];
    const float* f3  = (const float*)d_in[3];
    const float* pts = (const float*)d_in[4];
    const int*   bp  = (n_in >= 6) ? (const int*)d_in[5] : nullptr;

    int N = in_sizes[4] / 3;
    if (N > NPTS_MAX) N = NPTS_MAX;

    {
        int total = HWC_TOTAL + N;
        int threads = 256;
        int blocks = (total + threads - 1) / threads;
        prep_kernel<<<blocks, threads>>>(f0, f1, f2, f3, pts, bp, N);
    }
    {
        int blocks = (N + PTS_PER_BLK - 1) / PTS_PER_BLK;
        gather_kernel<<<blocks, 256>>>((float4*)d_out, N);
    }
}

// round 10
// speedup vs baseline: 1.6810x; 1.0008x over previous
#include <cuda_runtime.h>
#include <cuda_bf16.h>

// Scales: S={56,28,14,7}, C={64,128,256,512}, HW={3136,784,196,49}
// HWC scratch offsets (floats): 0, 200704, 301056, 351232; total 376320 floats.
#define HWC_TOTAL 376320
#define NPTS_MAX  131072
#define PTS_PER_BLK 16

__device__ float g_hwc[HWC_TOTAL];
__device__ int4  g_off[NPTS_MAX];   // per-point, per-scale float-offset of pixel base, -1 if zero row

// Pre-pass: (a) transpose batch-b CHW slices -> HWC scratch,
//           (b) per-point projected coords -> per-scale gather offsets (or -1).
__global__ void prep_kernel(const float* __restrict__ f0, const float* __restrict__ f1,
                            const float* __restrict__ f2, const float* __restrict__ f3,
                            const float* __restrict__ pts, const int* __restrict__ bptr,
                            int N)
{
    int tid = blockIdx.x * blockDim.x + threadIdx.x;
    if (tid < HWC_TOTAL) {
        int b = bptr ? *bptr : 3;
        const float* src; int e, clog2, HW;
        if (tid < 200704)      { src = f0; e = tid;          clog2 = 6; HW = 3136; }
        else if (tid < 301056) { src = f1; e = tid - 200704; clog2 = 7; HW = 784;  }
        else if (tid < 351232) { src = f2; e = tid - 301056; clog2 = 8; HW = 196;  }
        else                   { src = f3; e = tid - 351232; clog2 = 9; HW = 49;   }
        int C = 1 << clog2;
        int c = e & (C - 1);       // channel (fastest in dst)
        int p = e >> clog2;        // pixel index
        g_hwc[tid] = src[(size_t)b * C * HW + (size_t)c * HW + p];
    } else {
        int n = tid - HWC_TOTAL;
        if (n < N) {
            float p0 = pts[3 * n + 0];
            float p1 = pts[3 * n + 1];
            float p2 = pts[3 * n + 2];
            float h = 248.0f * (p1 / p2) + 111.5f;
            float w = 248.0f * (p0 / (-p2)) + 111.5f;
            h = fminf(fmaxf(h, 0.0f), 223.0f);
            w = fminf(fmaxf(w, 0.0f), 223.0f);

            const int   S[4]    = {56, 28, 14, 7};
            const int   C[4]    = {64, 128, 256, 512};
            const int   base[4] = {0, 200704, 301056, 351232};
            const float inv[4]  = {0.25f, 0.125f, 0.0625f, 0.03125f};

            int4 r;
            int* rp = (int*)&r;
            #pragma unroll
            for (int s = 0; s < 4; s++) {
                float x = h * inv[s];   // == h / (224/S): divisor is an exact power of two
                float y = w * inv[s];
                int x1 = (int)floorf(x);
                int y1 = (int)floorf(y);
                int x2 = min((int)ceilf(x), S[s] - 1);
                int y2 = min((int)ceilf(y), S[s] - 1);
                // reference truncates before weighting, so only w11=(x2-x1)*(y2-y1) in {0,1} survives
                int wgt = (x2 - x1) * (y2 - y1);
                rp[s] = wgt ? (base[s] + (x1 * S[s] + y1) * C[s]) : -1;
            }
            g_off[n] = r;
        }
    }
}

// Main kernel: each 256-thread block owns PTS_PER_BLK consecutive points.
// Per-point offsets are staged once into smem (1 LDS per point thereafter).
// Threads 0..239 each own a fixed float4 chunk of the 960-float row; the
// point loop is unrolled x8 so each thread keeps up to 8 independent L2-hit
// gathers in flight before 8 coalesced streaming stores.
// chunk [0,16): scale0; [16,48): scale1; [48,112): scale2; [112,240): scale3.
__global__ void __launch_bounds__(256) gather_kernel(float4* __restrict__ out, int N)
{
    __shared__ int4 s_off[PTS_PER_BLK];
    int tid = threadIdx.x;
    int p0 = blockIdx.x * PTS_PER_BLK;

    if (tid < PTS_PER_BLK && (p0 + tid) < N)
        s_off[tid] = g_off[p0 + tid];
    __syncthreads();

    if (tid >= 240) return;

    // Loop-invariant: which component of off4 this thread uses, and its chunk.
    int comp, c4;
    if (tid < 16)       { comp = 0; c4 = tid;       }
    else if (tid < 48)  { comp = 1; c4 = tid - 16;  }
    else if (tid < 112) { comp = 2; c4 = tid - 48;  }
    else                { comp = 3; c4 = tid - 112; }
    int c16 = c4 * 4;

    const float4 zero = make_float4(0.f, 0.f, 0.f, 0.f);

    if (p0 + PTS_PER_BLK <= N) {
        // Fast path: no bounds checks, 8 loads in flight.
        #pragma unroll 1
        for (int kb = 0; kb < PTS_PER_BLK; kb += 8) {
            float4 v[8];
            #pragma unroll
            for (int j = 0; j < 8; j++) {
                int4 o4 = s_off[kb + j];
                int off = (comp == 0) ? o4.x : (comp == 1) ? o4.y
                        : (comp == 2) ? o4.z : o4.w;
                v[j] = zero;
                if (off >= 0)
                    v[j] = __ldg((const float4*)&g_hwc[off + c16]);
            }
            float4* dst = out + (size_t)(p0 + kb) * 240 + tid;
            #pragma unroll
            for (int j = 0; j < 8; j++)
                __stcs(dst + (size_t)j * 240, v[j]);
        }
    } else {
        // Tail block: per-point bounds checks.
        for (int k = 0; k < PTS_PER_BLK; k++) {
            int p = p0 + k;
            if (p >= N) break;
            int4 o4 = s_off[k];
            int off = (comp == 0) ? o4.x : (comp == 1) ? o4.y
                    : (comp == 2) ? o4.z : o4.w;
            float4 v = zero;
            if (off >= 0)
                v = __ldg((const float4*)&g_hwc[off + c16]);
            __stcs(&out[(size_t)p * 240 + tid], v);
        }
    }
}

extern "C" void kernel_launch(void* const* d_in, const int* in_sizes, int n_in,
                              void* d_out, int out_size)
{
    const float* f0  = (const float*)d_in[0];
    const float* f1  = (const float*)d_in[1];
    const float* f2  = (const float*)d_in[2];
    const float* f3  = (const float*)d_in[3];
    const float* pts = (const float*)d_in[4];
    const int*   bp  = (n_in >= 6) ? (const int*)d_in[5] : nullptr;

    int N = in_sizes[4] / 3;
    if (N > NPTS_MAX) N = NPTS_MAX;

    {
        int total = HWC_TOTAL + N;
        int threads = 256;
        int blocks = (total + threads - 1) / threads;
        prep_kernel<<<blocks, threads>>>(f0, f1, f2, f3, pts, bp, N);
    }
    {
        int blocks = (N + PTS_PER_BLK - 1) / PTS_PER_BLK;
        gather_kernel<<<blocks, 256>>>((float4*)d_out, N);
    }
}